// round 5
// baseline (speedup 1.0000x reference)
#include <cuda_runtime.h>
#include <cstdint>

// ---------------------------------------------------------------------------
// Problem constants
//   SHAPE = (4, 8, 8, 4), I_CH=32, O_CH=128, BATCH=64, RANK=32
//   core0: (32, 64, 1, 4, 32)   strides (floats): i 8192, b 128, m 32, j 1
//   core1: (32, 64, 32, 8, 32)  strides: i 524288, b 8192, k 256, m 32, j 1
//   core2: same as core1
//   core3: (32, 64, 32, 4, 1)   strides: i 8192, b 128, k 4, m 1
//   weight:(32, 24, 128)        strides: i 3072, row 128, o 1
// ---------------------------------------------------------------------------

static const size_t Y0_OFF = 0;
static const size_t Y1_OFF = 1048576;
static const size_t Y2_OFF = 1048576 + 67108864ull;
static const size_t Y3_OFF = 1048576 + 2ull * 67108864ull;

// ---------------------------------------------------------------------------
// y0: out0[o,b,m,j] = sum_i W[i, m, o] * core0[i,b,0,m,j]
// ---------------------------------------------------------------------------
__global__ void __launch_bounds__(256) y0_kernel(
    const float* __restrict__ core0, const float* __restrict__ weight,
    float* __restrict__ out)
{
    __shared__ float cs[32 * 32];     // [i][j]
    __shared__ float Ws[32 * 128];    // [i][o]
    const int bm = blockIdx.x;
    const int b = bm >> 2;
    const int m = bm & 3;
    const int tid = threadIdx.x;

    {
        int i = tid >> 3, j4 = tid & 7;
        float4 v = *reinterpret_cast<const float4*>(
            core0 + (size_t)i * 8192 + b * 128 + m * 32 + j4 * 4);
        *reinterpret_cast<float4*>(&cs[i * 32 + j4 * 4]) = v;
    }
    #pragma unroll
    for (int q = 0; q < 4; ++q) {
        int idx = tid + 256 * q;
        int i = idx >> 5, o4 = idx & 31;
        float4 v = *reinterpret_cast<const float4*>(
            weight + (size_t)i * 3072 + m * 128 + o4 * 4);
        *reinterpret_cast<float4*>(&Ws[i * 128 + o4 * 4]) = v;
    }
    __syncthreads();

    const int j = tid & 31;
    const int obase = (tid >> 5) * 16;
    float acc[16];
    #pragma unroll
    for (int t = 0; t < 16; ++t) acc[t] = 0.f;
    #pragma unroll 4
    for (int i = 0; i < 32; ++i) {
        float v = cs[i * 32 + j];
        #pragma unroll
        for (int oo = 0; oo < 16; ++oo)
            acc[oo] = fmaf(Ws[i * 128 + obase + oo], v, acc[oo]);
    }
    #pragma unroll
    for (int oo = 0; oo < 16; ++oo)
        out[(size_t)(obase + oo) * 8192 + b * 128 + m * 32 + j] = acc[oo];
}

// ---------------------------------------------------------------------------
// y3: out3[o,b,k,m] = sum_i W[i, 20+m, o] * core3[i,b,k,m]
// ---------------------------------------------------------------------------
__global__ void __launch_bounds__(256) y3_kernel(
    const float* __restrict__ core3, const float* __restrict__ weight,
    float* __restrict__ out)
{
    __shared__ float cs[32 * 128];    // [i][km]
    __shared__ float Ws[32 * 32 * 4]; // [i][o_local][mm]
    const int b = blockIdx.x & 63;
    const int oq = blockIdx.x >> 6;
    const int tid = threadIdx.x;

    #pragma unroll
    for (int q = 0; q < 4; ++q) {
        int idx = tid + 256 * q;
        int i = idx >> 5, km4 = idx & 31;
        float4 v = *reinterpret_cast<const float4*>(
            core3 + (size_t)i * 8192 + b * 128 + km4 * 4);
        *reinterpret_cast<float4*>(&cs[i * 128 + km4 * 4]) = v;
    }
    #pragma unroll
    for (int q = 0; q < 16; ++q) {
        int idx = tid + 256 * q;
        int i = idx >> 7;
        int rem = idx & 127;
        int mm = rem >> 5;
        int ol = rem & 31;
        Ws[(i * 32 + ol) * 4 + mm] =
            weight[(size_t)i * 3072 + (20 + mm) * 128 + oq * 32 + ol];
    }
    __syncthreads();

    const int km = tid & 127;
    const int oh = tid >> 7;
    const int mm = km & 3;
    float acc[16];
    #pragma unroll
    for (int t = 0; t < 16; ++t) acc[t] = 0.f;
    #pragma unroll 4
    for (int i = 0; i < 32; ++i) {
        float v = cs[i * 128 + km];
        #pragma unroll
        for (int oo = 0; oo < 16; ++oo)
            acc[oo] = fmaf(Ws[(i * 32 + oh * 16 + oo) * 4 + mm], v, acc[oo]);
    }
    #pragma unroll
    for (int oo = 0; oo < 16; ++oo) {
        int o = oq * 32 + oh * 16 + oo;
        out[((size_t)o * 64 + b) * 128 + km] = acc[oo];
    }
}

// ---------------------------------------------------------------------------
// Fused cores 1 & 2:
//   A[o,k,j] = sum_i 0.5*W[i,off+m,o] * (c[i,b,j,m,k] - c[i,b,k,m,j])   (skew)
//   Q = (I-A)^{-1}(I+A) = 2*(I-A)^{-1} - I
// Phase 2 now uses BLOCKED Gauss-Jordan (panel width 8):
//   - mini in-place GJ on the 8 panel columns via shuffles (64 SHFL/panel);
//     afterwards those columns hold G[:,J] (the accumulated transform).
//   - panel rows broadcast through smem (stride-36 padded, conflict-free),
//     rank-8 update of the 24 remaining columns with float4 broadcast LDS.
// No pivoting needed: sym(I-A)=I  =>  every pivot >= 1.
// ---------------------------------------------------------------------------
__global__ void __launch_bounds__(512) cayley_kernel(
    const float* __restrict__ core1,
    const float* __restrict__ core2,
    const float* __restrict__ weight,
    float* __restrict__ out)
{
    const int og = blockIdx.x;            // 0..7   (o-group of 16)
    const int bm = blockIdx.y;            // 0..511
    const int b  = bm >> 3;
    const int m  = bm & 7;
    const int c  = blockIdx.z;            // 0..1
    const float* core = c ? core2 : core1;
    float* yout = out + (c ? Y2_OFF : Y1_OFF);
    const int woff = 4 + 8 * c;

    extern __shared__ float smem[];
    float* raw  = smem;                   // [8][32][33]  = 8448 floats (phase 1)
    float* Amat = smem + 8448;            // [16][32][33] = 16896 floats
    float* Ws   = smem + 8448 + 16896;    // [32][16]     = 512 floats
    // phase-2 panel-row broadcast buffer aliases the (then dead) raw region:
    // S[w][t][36]  -> 16 * 8 * 36 = 4608 floats  (stride 36 kills STS conflicts)

    const int tid = threadIdx.x;

    {   // 0.5*W slice
        int i  = tid >> 4;
        int oo = tid & 15;
        Ws[i * 16 + oo] =
            0.5f * weight[(size_t)i * 3072 + (woff + m) * 128 + og * 16 + oo];
    }

    // thread -> strict-upper-triangle pair (pk < pj)
    int pk = 0, pj = 0;
    if (tid < 496) {
        int rem = tid, k = 0;
        #pragma unroll 1
        while (rem >= 31 - k) { rem -= 31 - k; ++k; }
        pk = k;
        pj = k + 1 + rem;
    }

    float acc[16];
    #pragma unroll
    for (int oo = 0; oo < 16; ++oo) acc[oo] = 0.f;

    const float* cbase = core + (size_t)b * 8192 + m * 32;

    // --- phase 1: accumulate A upper triangle over i in chunks of 8 --------
    for (int ch = 0; ch < 4; ++ch) {
        __syncthreads();
        #pragma unroll
        for (int q = 0; q < 4; ++q) {
            int idx = tid + 512 * q;
            int il  = idx >> 8;
            int rem = idx & 255;
            int k   = rem >> 3;
            int j4  = rem & 7;
            const float4 v = *reinterpret_cast<const float4*>(
                cbase + (size_t)(ch * 8 + il) * 524288 + k * 256 + j4 * 4);
            float* d = &raw[(il * 32 + k) * 33 + j4 * 4];
            d[0] = v.x; d[1] = v.y; d[2] = v.z; d[3] = v.w;
        }
        __syncthreads();
        if (tid < 496) {
            #pragma unroll
            for (int il = 0; il < 8; ++il) {
                float dval = raw[(il * 32 + pj) * 33 + pk]
                           - raw[(il * 32 + pk) * 33 + pj];
                const float* wrow = &Ws[(ch * 8 + il) * 16];
                #pragma unroll
                for (int oo = 0; oo < 16; ++oo)
                    acc[oo] = fmaf(wrow[oo], dval, acc[oo]);
            }
        }
    }

    // --- mirror into smem A matrices ----------------------------------------
    if (tid < 496) {
        #pragma unroll
        for (int oo = 0; oo < 16; ++oo) {
            Amat[(oo * 32 + pk) * 33 + pj] = acc[oo];
            Amat[(oo * 32 + pj) * 33 + pk] = -acc[oo];
        }
    } else {
        int oo = tid - 496;
        #pragma unroll
        for (int dd = 0; dd < 32; ++dd)
            Amat[(oo * 32 + dd) * 33 + dd] = 0.f;
    }
    __syncthreads();

    // --- phase 2: per-warp blocked Gauss-Jordan inverse of M = I - A --------
    const int w    = tid >> 5;            // warp -> matrix index
    const int lane = tid & 31;            // lane -> row index

    float M[32];
    #pragma unroll
    for (int q = 0; q < 32; ++q)
        M[q] = (lane == q ? 1.0f : 0.0f) - Amat[(w * 32 + lane) * 33 + q];

    float* Sw = smem + w * 288;           // this warp's 8x36 panel buffer

    #pragma unroll
    for (int P = 0; P < 4; ++P) {
        // ---- mini in-place GJ on panel columns [8P, 8P+8) ----
        #pragma unroll
        for (int pp = 0; pp < 8; ++pp) {
            const int p = 8 * P + pp;
            float piv = __shfl_sync(0xffffffffu, M[p], p);
            float d   = __fdividef(1.0f, piv);     // pivots >= 1, safe
            float g   = (lane == p) ? (1.0f - d) : M[p] * d;
            #pragma unroll
            for (int qq = 0; qq < 8; ++qq) {
                const int q = 8 * P + qq;
                if (q == p) continue;
                float prq = __shfl_sync(0xffffffffu, M[q], p);
                M[q] = fmaf(-g, prq, M[q]);
            }
            M[p] = (lane == p) ? d : -g;
        }

        __syncwarp();   // prev panel's S reads done before overwrite
        // ---- write panel rows to smem (non-panel cols = pre-update values)
        if ((lane >> 3) == P) {
            float* srow = Sw + (lane & 7) * 36;
            #pragma unroll
            for (int g4 = 0; g4 < 8; ++g4) {
                float4 v = make_float4(M[g4 * 4 + 0], M[g4 * 4 + 1],
                                       M[g4 * 4 + 2], M[g4 * 4 + 3]);
                *reinterpret_cast<float4*>(srow + g4 * 4) = v;
            }
        }
        __syncwarp();

        // ---- panel lanes: new row = sum_t H[r,t] * S[t][:], start from 0
        if ((lane >> 3) == P) {
            #pragma unroll
            for (int g4 = 0; g4 < 8; ++g4) {
                if (g4 == 2 * P || g4 == 2 * P + 1) continue;
                M[g4 * 4 + 0] = 0.f; M[g4 * 4 + 1] = 0.f;
                M[g4 * 4 + 2] = 0.f; M[g4 * 4 + 3] = 0.f;
            }
        }

        // ---- rank-8 update of the 24 non-panel columns (broadcast LDS.128)
        #pragma unroll
        for (int t = 0; t < 8; ++t) {
            float h = M[8 * P + t];                   // G[r, 8P+t] (register)
            const float4* srow = reinterpret_cast<const float4*>(Sw + t * 36);
            #pragma unroll
            for (int g4 = 0; g4 < 8; ++g4) {
                if (g4 == 2 * P || g4 == 2 * P + 1) continue;
                float4 s = srow[g4];
                M[g4 * 4 + 0] = fmaf(h, s.x, M[g4 * 4 + 0]);
                M[g4 * 4 + 1] = fmaf(h, s.y, M[g4 * 4 + 1]);
                M[g4 * 4 + 2] = fmaf(h, s.z, M[g4 * 4 + 2]);
                M[g4 * 4 + 3] = fmaf(h, s.w, M[g4 * 4 + 3]);
            }
        }
    }

    // --- Q = 2*Minv - I ; write row 'lane' of matrix (o, b, m) --------------
    const int o = og * 16 + w;
    float* dst = yout + ((size_t)o * 64 + b) * 8192 + lane * 256 + m * 32;
    #pragma unroll
    for (int qq = 0; qq < 8; ++qq) {
        float4 v;
        v.x = 2.f * M[qq * 4 + 0] - (lane == qq * 4 + 0 ? 1.f : 0.f);
        v.y = 2.f * M[qq * 4 + 1] - (lane == qq * 4 + 1 ? 1.f : 0.f);
        v.z = 2.f * M[qq * 4 + 2] - (lane == qq * 4 + 2 ? 1.f : 0.f);
        v.w = 2.f * M[qq * 4 + 3] - (lane == qq * 4 + 3 ? 1.f : 0.f);
        *reinterpret_cast<float4*>(dst + qq * 4) = v;
    }
}

// ---------------------------------------------------------------------------
extern "C" void kernel_launch(void* const* d_in, const int* in_sizes, int n_in,
                              void* d_out, int out_size)
{
    (void)in_sizes; (void)n_in; (void)out_size;
    const float* core0  = (const float*)d_in[0];
    const float* core1  = (const float*)d_in[1];
    const float* core2  = (const float*)d_in[2];
    const float* core3  = (const float*)d_in[3];
    const float* weight = (const float*)d_in[4];
    float* out = (float*)d_out;

    static const int SMEM_BYTES = (8448 + 16896 + 512) * 4;   // 103424 B
    cudaFuncSetAttribute(cayley_kernel,
                         cudaFuncAttributeMaxDynamicSharedMemorySize,
                         SMEM_BYTES);

    y0_kernel<<<256, 256>>>(core0, weight, out + Y0_OFF);
    y3_kernel<<<256, 256>>>(core3, weight, out + Y3_OFF);
    cayley_kernel<<<dim3(8, 512, 2), 512, SMEM_BYTES>>>(core1, core2, weight, out);
}

// round 6
// speedup vs baseline: 1.3062x; 1.3062x over previous
#include <cuda_runtime.h>
#include <cstdint>

// ---------------------------------------------------------------------------
// Problem constants
//   SHAPE = (4, 8, 8, 4), I_CH=32, O_CH=128, BATCH=64, RANK=32
//   core0: (32, 64, 1, 4, 32)   strides (floats): i 8192, b 128, m 32, j 1
//   core1: (32, 64, 32, 8, 32)  strides: i 524288, b 8192, k 256, m 32, j 1
//   core2: same as core1
//   core3: (32, 64, 32, 4, 1)   strides: i 8192, b 128, k 4, m 1
//   weight:(32, 24, 128)        strides: i 3072, row 128, o 1
// ---------------------------------------------------------------------------

static const size_t Y0_OFF = 0;
static const size_t Y1_OFF = 1048576;
static const size_t Y2_OFF = 1048576 + 67108864ull;
static const size_t Y3_OFF = 1048576 + 2ull * 67108864ull;

// ---------------------------------------------------------------------------
// y0: out0[o,b,m,j] = sum_i W[i, m, o] * core0[i,b,0,m,j]
// ---------------------------------------------------------------------------
__global__ void __launch_bounds__(256) y0_kernel(
    const float* __restrict__ core0, const float* __restrict__ weight,
    float* __restrict__ out)
{
    __shared__ float cs[32 * 32];     // [i][j]
    __shared__ float Ws[32 * 128];    // [i][o]
    const int bm = blockIdx.x;
    const int b = bm >> 2;
    const int m = bm & 3;
    const int tid = threadIdx.x;

    {
        int i = tid >> 3, j4 = tid & 7;
        float4 v = *reinterpret_cast<const float4*>(
            core0 + (size_t)i * 8192 + b * 128 + m * 32 + j4 * 4);
        *reinterpret_cast<float4*>(&cs[i * 32 + j4 * 4]) = v;
    }
    #pragma unroll
    for (int q = 0; q < 4; ++q) {
        int idx = tid + 256 * q;
        int i = idx >> 5, o4 = idx & 31;
        float4 v = *reinterpret_cast<const float4*>(
            weight + (size_t)i * 3072 + m * 128 + o4 * 4);
        *reinterpret_cast<float4*>(&Ws[i * 128 + o4 * 4]) = v;
    }
    __syncthreads();

    const int j = tid & 31;
    const int obase = (tid >> 5) * 16;
    float acc[16];
    #pragma unroll
    for (int t = 0; t < 16; ++t) acc[t] = 0.f;
    #pragma unroll 4
    for (int i = 0; i < 32; ++i) {
        float v = cs[i * 32 + j];
        #pragma unroll
        for (int oo = 0; oo < 16; ++oo)
            acc[oo] = fmaf(Ws[i * 128 + obase + oo], v, acc[oo]);
    }
    #pragma unroll
    for (int oo = 0; oo < 16; ++oo)
        out[(size_t)(obase + oo) * 8192 + b * 128 + m * 32 + j] = acc[oo];
}

// ---------------------------------------------------------------------------
// y3: out3[o,b,k,m] = sum_i W[i, 20+m, o] * core3[i,b,k,m]
// ---------------------------------------------------------------------------
__global__ void __launch_bounds__(256) y3_kernel(
    const float* __restrict__ core3, const float* __restrict__ weight,
    float* __restrict__ out)
{
    __shared__ float cs[32 * 128];    // [i][km]
    __shared__ float Ws[32 * 32 * 4]; // [i][o_local][mm]
    const int b = blockIdx.x & 63;
    const int oq = blockIdx.x >> 6;
    const int tid = threadIdx.x;

    #pragma unroll
    for (int q = 0; q < 4; ++q) {
        int idx = tid + 256 * q;
        int i = idx >> 5, km4 = idx & 31;
        float4 v = *reinterpret_cast<const float4*>(
            core3 + (size_t)i * 8192 + b * 128 + km4 * 4);
        *reinterpret_cast<float4*>(&cs[i * 128 + km4 * 4]) = v;
    }
    #pragma unroll
    for (int q = 0; q < 16; ++q) {
        int idx = tid + 256 * q;
        int i = idx >> 7;
        int rem = idx & 127;
        int mm = rem >> 5;
        int ol = rem & 31;
        Ws[(i * 32 + ol) * 4 + mm] =
            weight[(size_t)i * 3072 + (20 + mm) * 128 + oq * 32 + ol];
    }
    __syncthreads();

    const int km = tid & 127;
    const int oh = tid >> 7;
    const int mm = km & 3;
    float acc[16];
    #pragma unroll
    for (int t = 0; t < 16; ++t) acc[t] = 0.f;
    #pragma unroll 4
    for (int i = 0; i < 32; ++i) {
        float v = cs[i * 128 + km];
        #pragma unroll
        for (int oo = 0; oo < 16; ++oo)
            acc[oo] = fmaf(Ws[(i * 32 + oh * 16 + oo) * 4 + mm], v, acc[oo]);
    }
    #pragma unroll
    for (int oo = 0; oo < 16; ++oo) {
        int o = oq * 32 + oh * 16 + oo;
        out[((size_t)o * 64 + b) * 128 + km] = acc[oo];
    }
}

// ---------------------------------------------------------------------------
// Fused cores 1 & 2:
//   A[o,k,j] = sum_i 0.5*W[i,off+m,o] * (c[i,b,j,m,k] - c[i,b,k,m,j])   (skew)
//   Q = (I-A)^{-1}(I+A) = 2*(I-A)^{-1} - I
// Phase 2: per-warp register Gauss-Jordan (row-per-lane), but the pivot row
// is broadcast through a double-buffered smem row (8 STS.128 by the owner
// lane, 8 broadcast LDS.128 by everyone) instead of 31 shuffles per pivot.
// Arithmetic identical to the plain shuffle version.
// No pivoting needed: sym(I-A)=I  =>  every pivot >= 1.
// ---------------------------------------------------------------------------
__global__ void __launch_bounds__(512) cayley_kernel(
    const float* __restrict__ core1,
    const float* __restrict__ core2,
    const float* __restrict__ weight,
    float* __restrict__ out)
{
    const int og = blockIdx.x;            // 0..7   (o-group of 16)
    const int bm = blockIdx.y;            // 0..511
    const int b  = bm >> 3;
    const int m  = bm & 7;
    const int c  = blockIdx.z;            // 0..1
    const float* core = c ? core2 : core1;
    float* yout = out + (c ? Y2_OFF : Y1_OFF);
    const int woff = 4 + 8 * c;

    extern __shared__ float smem[];
    float* raw  = smem;                   // [8][32][33]  = 8448 floats (phase 1)
    float* Amat = smem + 8448;            // [16][32][33] = 16896 floats
    float* Ws   = smem + 8448 + 16896;    // [32][16]     = 512 floats
    // phase-2 pivot-row buffers alias the (then dead) raw region:
    //   per warp: 2 buffers x 36 floats = 72 floats; 16 warps -> 1152 floats

    const int tid = threadIdx.x;

    {   // 0.5*W slice
        int i  = tid >> 4;
        int oo = tid & 15;
        Ws[i * 16 + oo] =
            0.5f * weight[(size_t)i * 3072 + (woff + m) * 128 + og * 16 + oo];
    }

    // thread -> strict-upper-triangle pair (pk < pj)
    int pk = 0, pj = 0;
    if (tid < 496) {
        int rem = tid, k = 0;
        #pragma unroll 1
        while (rem >= 31 - k) { rem -= 31 - k; ++k; }
        pk = k;
        pj = k + 1 + rem;
    }

    float acc[16];
    #pragma unroll
    for (int oo = 0; oo < 16; ++oo) acc[oo] = 0.f;

    const float* cbase = core + (size_t)b * 8192 + m * 32;

    // --- phase 1: accumulate A upper triangle over i in chunks of 8 --------
    for (int ch = 0; ch < 4; ++ch) {
        __syncthreads();
        #pragma unroll
        for (int q = 0; q < 4; ++q) {
            int idx = tid + 512 * q;
            int il  = idx >> 8;
            int rem = idx & 255;
            int k   = rem >> 3;
            int j4  = rem & 7;
            const float4 v = *reinterpret_cast<const float4*>(
                cbase + (size_t)(ch * 8 + il) * 524288 + k * 256 + j4 * 4);
            float* d = &raw[(il * 32 + k) * 33 + j4 * 4];
            d[0] = v.x; d[1] = v.y; d[2] = v.z; d[3] = v.w;
        }
        __syncthreads();
        if (tid < 496) {
            #pragma unroll
            for (int il = 0; il < 8; ++il) {
                float dval = raw[(il * 32 + pj) * 33 + pk]
                           - raw[(il * 32 + pk) * 33 + pj];
                const float* wrow = &Ws[(ch * 8 + il) * 16];
                #pragma unroll
                for (int oo = 0; oo < 16; ++oo)
                    acc[oo] = fmaf(wrow[oo], dval, acc[oo]);
            }
        }
    }

    // --- mirror into smem A matrices ----------------------------------------
    if (tid < 496) {
        #pragma unroll
        for (int oo = 0; oo < 16; ++oo) {
            Amat[(oo * 32 + pk) * 33 + pj] = acc[oo];
            Amat[(oo * 32 + pj) * 33 + pk] = -acc[oo];
        }
    } else {
        int oo = tid - 496;
        #pragma unroll
        for (int dd = 0; dd < 32; ++dd)
            Amat[(oo * 32 + dd) * 33 + dd] = 0.f;
    }
    __syncthreads();

    // --- phase 2: per-warp register Gauss-Jordan inverse of M = I - A ------
    const int w    = tid >> 5;            // warp -> matrix index
    const int lane = tid & 31;            // lane -> row index

    float M[32];
    #pragma unroll
    for (int q = 0; q < 32; ++q)
        M[q] = (lane == q ? 1.0f : 0.0f) - Amat[(w * 32 + lane) * 33 + q];

    float* Sw = smem + w * 72;            // 2 x 36-float pivot-row buffers

    #pragma unroll
    for (int p = 0; p < 32; ++p) {
        float* buf = Sw + (p & 1) * 36;
        if (lane == p) {                  // publish pre-update pivot row
            #pragma unroll
            for (int g4 = 0; g4 < 8; ++g4)
                *reinterpret_cast<float4*>(buf + g4 * 4) =
                    make_float4(M[g4 * 4 + 0], M[g4 * 4 + 1],
                                M[g4 * 4 + 2], M[g4 * 4 + 3]);
        }
        __syncwarp();
        float piv = buf[p];               // broadcast scalar LDS
        float d   = __fdividef(1.0f, piv);       // pivots >= 1, always safe
        float g   = (lane == p) ? (1.0f - d) : M[p] * d;
        #pragma unroll
        for (int g4 = 0; g4 < 8; ++g4) {  // unconditional rank-1 update;
            float4 s = *reinterpret_cast<const float4*>(buf + g4 * 4);
            M[g4 * 4 + 0] = fmaf(-g, s.x, M[g4 * 4 + 0]);
            M[g4 * 4 + 1] = fmaf(-g, s.y, M[g4 * 4 + 1]);
            M[g4 * 4 + 2] = fmaf(-g, s.z, M[g4 * 4 + 2]);
            M[g4 * 4 + 3] = fmaf(-g, s.w, M[g4 * 4 + 3]);
        }
        M[p] = (lane == p) ? d : -g;      // column p overwritten (fixes q==p)
    }

    // --- Q = 2*Minv - I ; write row 'lane' of matrix (o, b, m) --------------
    const int o = og * 16 + w;
    float* dst = yout + ((size_t)o * 64 + b) * 8192 + lane * 256 + m * 32;
    #pragma unroll
    for (int qq = 0; qq < 8; ++qq) {
        float4 v;
        v.x = 2.f * M[qq * 4 + 0] - (lane == qq * 4 + 0 ? 1.f : 0.f);
        v.y = 2.f * M[qq * 4 + 1] - (lane == qq * 4 + 1 ? 1.f : 0.f);
        v.z = 2.f * M[qq * 4 + 2] - (lane == qq * 4 + 2 ? 1.f : 0.f);
        v.w = 2.f * M[qq * 4 + 3] - (lane == qq * 4 + 3 ? 1.f : 0.f);
        *reinterpret_cast<float4*>(dst + qq * 4) = v;
    }
}

// ---------------------------------------------------------------------------
extern "C" void kernel_launch(void* const* d_in, const int* in_sizes, int n_in,
                              void* d_out, int out_size)
{
    (void)in_sizes; (void)n_in; (void)out_size;
    const float* core0  = (const float*)d_in[0];
    const float* core1  = (const float*)d_in[1];
    const float* core2  = (const float*)d_in[2];
    const float* core3  = (const float*)d_in[3];
    const float* weight = (const float*)d_in[4];
    float* out = (float*)d_out;

    static const int SMEM_BYTES = (8448 + 16896 + 512) * 4;   // 103424 B
    cudaFuncSetAttribute(cayley_kernel,
                         cudaFuncAttributeMaxDynamicSharedMemorySize,
                         SMEM_BYTES);

    y0_kernel<<<256, 256>>>(core0, weight, out + Y0_OFF);
    y3_kernel<<<256, 256>>>(core3, weight, out + Y3_OFF);
    cayley_kernel<<<dim3(8, 512, 2), 512, SMEM_BYTES>>>(core1, core2, weight, out);
}

// round 7
// speedup vs baseline: 1.5489x; 1.1859x over previous
#include <cuda_runtime.h>
#include <cstdint>

// ---------------------------------------------------------------------------
// Problem constants
//   SHAPE = (4, 8, 8, 4), I_CH=32, O_CH=128, BATCH=64, RANK=32
//   core0: (32, 64, 1, 4, 32)   strides (floats): i 8192, b 128, m 32, j 1
//   core1: (32, 64, 32, 8, 32)  strides: i 524288, b 8192, k 256, m 32, j 1
//   core2: same as core1
//   core3: (32, 64, 32, 4, 1)   strides: i 8192, b 128, k 4, m 1
//   weight:(32, 24, 128)        strides: i 3072, row 128, o 1
// ---------------------------------------------------------------------------

static const size_t Y0_OFF = 0;
static const size_t Y1_OFF = 1048576;
static const size_t Y2_OFF = 1048576 + 67108864ull;
static const size_t Y3_OFF = 1048576 + 2ull * 67108864ull;

// ---------------------------------------------------------------------------
// y0: out0[o,b,m,j] = sum_i W[i, m, o] * core0[i,b,0,m,j]
// ---------------------------------------------------------------------------
__global__ void __launch_bounds__(256) y0_kernel(
    const float* __restrict__ core0, const float* __restrict__ weight,
    float* __restrict__ out)
{
    __shared__ float cs[32 * 32];     // [i][j]
    __shared__ float Ws[32 * 128];    // [i][o]
    const int bm = blockIdx.x;
    const int b = bm >> 2;
    const int m = bm & 3;
    const int tid = threadIdx.x;

    {
        int i = tid >> 3, j4 = tid & 7;
        float4 v = *reinterpret_cast<const float4*>(
            core0 + (size_t)i * 8192 + b * 128 + m * 32 + j4 * 4);
        *reinterpret_cast<float4*>(&cs[i * 32 + j4 * 4]) = v;
    }
    #pragma unroll
    for (int q = 0; q < 4; ++q) {
        int idx = tid + 256 * q;
        int i = idx >> 5, o4 = idx & 31;
        float4 v = *reinterpret_cast<const float4*>(
            weight + (size_t)i * 3072 + m * 128 + o4 * 4);
        *reinterpret_cast<float4*>(&Ws[i * 128 + o4 * 4]) = v;
    }
    __syncthreads();

    const int j = tid & 31;
    const int obase = (tid >> 5) * 16;
    float acc[16];
    #pragma unroll
    for (int t = 0; t < 16; ++t) acc[t] = 0.f;
    #pragma unroll 4
    for (int i = 0; i < 32; ++i) {
        float v = cs[i * 32 + j];
        #pragma unroll
        for (int oo = 0; oo < 16; ++oo)
            acc[oo] = fmaf(Ws[i * 128 + obase + oo], v, acc[oo]);
    }
    #pragma unroll
    for (int oo = 0; oo < 16; ++oo)
        out[(size_t)(obase + oo) * 8192 + b * 128 + m * 32 + j] = acc[oo];
}

// ---------------------------------------------------------------------------
// y3: out3[o,b,k,m] = sum_i W[i, 20+m, o] * core3[i,b,k,m]
// ---------------------------------------------------------------------------
__global__ void __launch_bounds__(256) y3_kernel(
    const float* __restrict__ core3, const float* __restrict__ weight,
    float* __restrict__ out)
{
    __shared__ float cs[32 * 128];    // [i][km]
    __shared__ float Ws[32 * 32 * 4]; // [i][o_local][mm]
    const int b = blockIdx.x & 63;
    const int oq = blockIdx.x >> 6;
    const int tid = threadIdx.x;

    #pragma unroll
    for (int q = 0; q < 4; ++q) {
        int idx = tid + 256 * q;
        int i = idx >> 5, km4 = idx & 31;
        float4 v = *reinterpret_cast<const float4*>(
            core3 + (size_t)i * 8192 + b * 128 + km4 * 4);
        *reinterpret_cast<float4*>(&cs[i * 128 + km4 * 4]) = v;
    }
    #pragma unroll
    for (int q = 0; q < 16; ++q) {
        int idx = tid + 256 * q;
        int i = idx >> 7;
        int rem = idx & 127;
        int mm = rem >> 5;
        int ol = rem & 31;
        Ws[(i * 32 + ol) * 4 + mm] =
            weight[(size_t)i * 3072 + (20 + mm) * 128 + oq * 32 + ol];
    }
    __syncthreads();

    const int km = tid & 127;
    const int oh = tid >> 7;
    const int mm = km & 3;
    float acc[16];
    #pragma unroll
    for (int t = 0; t < 16; ++t) acc[t] = 0.f;
    #pragma unroll 4
    for (int i = 0; i < 32; ++i) {
        float v = cs[i * 128 + km];
        #pragma unroll
        for (int oo = 0; oo < 16; ++oo)
            acc[oo] = fmaf(Ws[(i * 32 + oh * 16 + oo) * 4 + mm], v, acc[oo]);
    }
    #pragma unroll
    for (int oo = 0; oo < 16; ++oo) {
        int o = oq * 32 + oh * 16 + oo;
        out[((size_t)o * 64 + b) * 128 + km] = acc[oo];
    }
}

// ---------------------------------------------------------------------------
// Fused cores 1 & 2:
//   A[o,k,j] = sum_i 0.5*W[i,off+m,o] * (c[i,b,j,m,k] - c[i,b,k,m,j])   (skew)
//   Q = (I-A)^{-1}(I+A) = 2*(I-A)^{-1} - I
// Phase 2: per-warp register Gauss-Jordan, row-per-lane, shuffle pivot
// broadcast (round-3 form, bit-identical arithmetic).
// __launch_bounds__(512, 2): cap regs at 64 so 2 CTAs/SM co-reside
// (2 x 103.4 KB smem fits the 228 KB carveout) -> 32 warps/SM to hide the
// SHFL->FMA dependency latency that dominated at 16 warps/SM.
// No pivoting needed: sym(I-A)=I  =>  every pivot >= 1.
// ---------------------------------------------------------------------------
__global__ void __launch_bounds__(512, 2) cayley_kernel(
    const float* __restrict__ core1,
    const float* __restrict__ core2,
    const float* __restrict__ weight,
    float* __restrict__ out)
{
    const int og = blockIdx.x;            // 0..7   (o-group of 16)
    const int bm = blockIdx.y;            // 0..511
    const int b  = bm >> 3;
    const int m  = bm & 7;
    const int c  = blockIdx.z;            // 0..1
    const float* core = c ? core2 : core1;
    float* yout = out + (c ? Y2_OFF : Y1_OFF);
    const int woff = 4 + 8 * c;

    extern __shared__ float smem[];
    float* raw  = smem;                   // [8][32][33]  = 8448 floats (phase 1)
    float* Amat = smem + 8448;            // [16][32][33] = 16896 floats
    float* Ws   = smem + 8448 + 16896;    // [32][16]     = 512 floats

    const int tid = threadIdx.x;

    {   // 0.5*W slice
        int i  = tid >> 4;
        int oo = tid & 15;
        Ws[i * 16 + oo] =
            0.5f * weight[(size_t)i * 3072 + (woff + m) * 128 + og * 16 + oo];
    }

    // thread -> strict-upper-triangle pair (pk < pj)
    int pk = 0, pj = 0;
    if (tid < 496) {
        int rem = tid, k = 0;
        #pragma unroll 1
        while (rem >= 31 - k) { rem -= 31 - k; ++k; }
        pk = k;
        pj = k + 1 + rem;
    }

    float acc[16];
    #pragma unroll
    for (int oo = 0; oo < 16; ++oo) acc[oo] = 0.f;

    const float* cbase = core + (size_t)b * 8192 + m * 32;

    // --- phase 1: accumulate A upper triangle over i in chunks of 8 --------
    for (int ch = 0; ch < 4; ++ch) {
        __syncthreads();
        #pragma unroll
        for (int q = 0; q < 4; ++q) {
            int idx = tid + 512 * q;
            int il  = idx >> 8;
            int rem = idx & 255;
            int k   = rem >> 3;
            int j4  = rem & 7;
            const float4 v = *reinterpret_cast<const float4*>(
                cbase + (size_t)(ch * 8 + il) * 524288 + k * 256 + j4 * 4);
            float* d = &raw[(il * 32 + k) * 33 + j4 * 4];
            d[0] = v.x; d[1] = v.y; d[2] = v.z; d[3] = v.w;
        }
        __syncthreads();
        if (tid < 496) {
            #pragma unroll
            for (int il = 0; il < 8; ++il) {
                float dval = raw[(il * 32 + pj) * 33 + pk]
                           - raw[(il * 32 + pk) * 33 + pj];
                const float* wrow = &Ws[(ch * 8 + il) * 16];
                #pragma unroll
                for (int oo = 0; oo < 16; ++oo)
                    acc[oo] = fmaf(wrow[oo], dval, acc[oo]);
            }
        }
    }

    // --- mirror into smem A matrices ----------------------------------------
    if (tid < 496) {
        #pragma unroll
        for (int oo = 0; oo < 16; ++oo) {
            Amat[(oo * 32 + pk) * 33 + pj] = acc[oo];
            Amat[(oo * 32 + pj) * 33 + pk] = -acc[oo];
        }
    } else {
        int oo = tid - 496;
        #pragma unroll
        for (int dd = 0; dd < 32; ++dd)
            Amat[(oo * 32 + dd) * 33 + dd] = 0.f;
    }
    __syncthreads();

    // --- phase 2: per-warp register Gauss-Jordan inverse of M = I - A ------
    const int w    = tid >> 5;            // warp -> matrix index
    const int lane = tid & 31;            // lane -> row index

    float M[32];
    #pragma unroll
    for (int q = 0; q < 32; ++q)
        M[q] = (lane == q ? 1.0f : 0.0f) - Amat[(w * 32 + lane) * 33 + q];

    #pragma unroll
    for (int p = 0; p < 32; ++p) {
        float piv = __shfl_sync(0xffffffffu, M[p], p);
        float d   = __fdividef(1.0f, piv);        // pivots >= 1, always safe
        float g   = (lane == p) ? (1.0f - d) : M[p] * d;
        #pragma unroll
        for (int q = 0; q < 32; ++q) {
            if (q == p) continue;
            float prq = __shfl_sync(0xffffffffu, M[q], p);
            M[q] = fmaf(-g, prq, M[q]);
        }
        M[p] = (lane == p) ? d : -g;
    }

    // --- Q = 2*Minv - I ; write row 'lane' of matrix (o, b, m) --------------
    const int o = og * 16 + w;
    float* dst = yout + ((size_t)o * 64 + b) * 8192 + lane * 256 + m * 32;
    #pragma unroll
    for (int qq = 0; qq < 8; ++qq) {
        float4 v;
        v.x = 2.f * M[qq * 4 + 0] - (lane == qq * 4 + 0 ? 1.f : 0.f);
        v.y = 2.f * M[qq * 4 + 1] - (lane == qq * 4 + 1 ? 1.f : 0.f);
        v.z = 2.f * M[qq * 4 + 2] - (lane == qq * 4 + 2 ? 1.f : 0.f);
        v.w = 2.f * M[qq * 4 + 3] - (lane == qq * 4 + 3 ? 1.f : 0.f);
        *reinterpret_cast<float4*>(dst + qq * 4) = v;
    }
}

// ---------------------------------------------------------------------------
extern "C" void kernel_launch(void* const* d_in, const int* in_sizes, int n_in,
                              void* d_out, int out_size)
{
    (void)in_sizes; (void)n_in; (void)out_size;
    const float* core0  = (const float*)d_in[0];
    const float* core1  = (const float*)d_in[1];
    const float* core2  = (const float*)d_in[2];
    const float* core3  = (const float*)d_in[3];
    const float* weight = (const float*)d_in[4];
    float* out = (float*)d_out;

    static const int SMEM_BYTES = (8448 + 16896 + 512) * 4;   // 103424 B
    cudaFuncSetAttribute(cayley_kernel,
                         cudaFuncAttributeMaxDynamicSharedMemorySize,
                         SMEM_BYTES);

    y0_kernel<<<256, 256>>>(core0, weight, out + Y0_OFF);
    y3_kernel<<<256, 256>>>(core3, weight, out + Y3_OFF);
    cayley_kernel<<<dim3(8, 512, 2), 512, SMEM_BYTES>>>(core1, core2, weight, out);
}

// round 8
// speedup vs baseline: 1.8283x; 1.1803x over previous
#include <cuda_runtime.h>
#include <cstdint>

// ---------------------------------------------------------------------------
// Problem constants
//   SHAPE = (4, 8, 8, 4), I_CH=32, O_CH=128, BATCH=64, RANK=32
//   core0: (32, 64, 1, 4, 32)   strides (floats): i 8192, b 128, m 32, j 1
//   core1: (32, 64, 32, 8, 32)  strides: i 524288, b 8192, k 256, m 32, j 1
//   core2: same as core1
//   core3: (32, 64, 32, 4, 1)   strides: i 8192, b 128, k 4, m 1
//   weight:(32, 24, 128)        strides: i 3072, row 128, o 1
// ---------------------------------------------------------------------------

static const size_t Y0_OFF = 0;
static const size_t Y1_OFF = 1048576;
static const size_t Y2_OFF = 1048576 + 67108864ull;
static const size_t Y3_OFF = 1048576 + 2ull * 67108864ull;

// ---------------------------------------------------------------------------
// y0: out0[o,b,m,j] = sum_i W[i, m, o] * core0[i,b,0,m,j]
// ---------------------------------------------------------------------------
__global__ void __launch_bounds__(256) y0_kernel(
    const float* __restrict__ core0, const float* __restrict__ weight,
    float* __restrict__ out)
{
    __shared__ float cs[32 * 32];     // [i][j]
    __shared__ float Ws[32 * 128];    // [i][o]
    const int bm = blockIdx.x;
    const int b = bm >> 2;
    const int m = bm & 3;
    const int tid = threadIdx.x;

    {
        int i = tid >> 3, j4 = tid & 7;
        float4 v = *reinterpret_cast<const float4*>(
            core0 + (size_t)i * 8192 + b * 128 + m * 32 + j4 * 4);
        *reinterpret_cast<float4*>(&cs[i * 32 + j4 * 4]) = v;
    }
    #pragma unroll
    for (int q = 0; q < 4; ++q) {
        int idx = tid + 256 * q;
        int i = idx >> 5, o4 = idx & 31;
        float4 v = *reinterpret_cast<const float4*>(
            weight + (size_t)i * 3072 + m * 128 + o4 * 4);
        *reinterpret_cast<float4*>(&Ws[i * 128 + o4 * 4]) = v;
    }
    __syncthreads();

    const int j = tid & 31;
    const int obase = (tid >> 5) * 16;
    float acc[16];
    #pragma unroll
    for (int t = 0; t < 16; ++t) acc[t] = 0.f;
    #pragma unroll 4
    for (int i = 0; i < 32; ++i) {
        float v = cs[i * 32 + j];
        #pragma unroll
        for (int oo = 0; oo < 16; ++oo)
            acc[oo] = fmaf(Ws[i * 128 + obase + oo], v, acc[oo]);
    }
    #pragma unroll
    for (int oo = 0; oo < 16; ++oo)
        out[(size_t)(obase + oo) * 8192 + b * 128 + m * 32 + j] = acc[oo];
}

// ---------------------------------------------------------------------------
// y3: out3[o,b,k,m] = sum_i W[i, 20+m, o] * core3[i,b,k,m]
// ---------------------------------------------------------------------------
__global__ void __launch_bounds__(256) y3_kernel(
    const float* __restrict__ core3, const float* __restrict__ weight,
    float* __restrict__ out)
{
    __shared__ float cs[32 * 128];    // [i][km]
    __shared__ float Ws[32 * 32 * 4]; // [i][o_local][mm]
    const int b = blockIdx.x & 63;
    const int oq = blockIdx.x >> 6;
    const int tid = threadIdx.x;

    #pragma unroll
    for (int q = 0; q < 4; ++q) {
        int idx = tid + 256 * q;
        int i = idx >> 5, km4 = idx & 31;
        float4 v = *reinterpret_cast<const float4*>(
            core3 + (size_t)i * 8192 + b * 128 + km4 * 4);
        *reinterpret_cast<float4*>(&cs[i * 128 + km4 * 4]) = v;
    }
    #pragma unroll
    for (int q = 0; q < 16; ++q) {
        int idx = tid + 256 * q;
        int i = idx >> 7;
        int rem = idx & 127;
        int mm = rem >> 5;
        int ol = rem & 31;
        Ws[(i * 32 + ol) * 4 + mm] =
            weight[(size_t)i * 3072 + (20 + mm) * 128 + oq * 32 + ol];
    }
    __syncthreads();

    const int km = tid & 127;
    const int oh = tid >> 7;
    const int mm = km & 3;
    float acc[16];
    #pragma unroll
    for (int t = 0; t < 16; ++t) acc[t] = 0.f;
    #pragma unroll 4
    for (int i = 0; i < 32; ++i) {
        float v = cs[i * 128 + km];
        #pragma unroll
        for (int oo = 0; oo < 16; ++oo)
            acc[oo] = fmaf(Ws[(i * 32 + oh * 16 + oo) * 4 + mm], v, acc[oo]);
    }
    #pragma unroll
    for (int oo = 0; oo < 16; ++oo) {
        int o = oq * 32 + oh * 16 + oo;
        out[((size_t)o * 64 + b) * 128 + km] = acc[oo];
    }
}

// ---------------------------------------------------------------------------
// Fused cores 1 & 2:
//   A[o,k,j] = sum_i 0.5*W[i,off+m,o] * (c[i,b,j,m,k] - c[i,b,k,m,j])   (skew)
//   Q = (I-A)^{-1}(I+A) = 2*(I-A)^{-1} - I
// Phase 2: per-warp BLOCKED register Gauss-Jordan (panel width 8):
//   - publish panel rows (pre-mini-GJ) to a double-buffered warp-private
//     smem buffer (aliased onto this warp's own dead Amat rows);
//   - mini-GJ restricted to the 8 panel columns: 8 SHFL per pivot (4x fewer
//     shuffles than full-row broadcast). In-place identity => panel columns
//     then hold the accumulated transform E[:,J];
//   - rank-8 update of the 24 non-panel columns with broadcast LDS.128 +
//     FMA; panel lanes handled branch-free via keep in {0,1}.
// One __syncwarp per panel. __launch_bounds__(512,2) keeps 2 CTAs/SM.
// No pivoting needed: sym(I-A)=I  =>  every pivot >= 1.
// ---------------------------------------------------------------------------
__global__ void __launch_bounds__(512, 2) cayley_kernel(
    const float* __restrict__ core1,
    const float* __restrict__ core2,
    const float* __restrict__ weight,
    float* __restrict__ out)
{
    const int og = blockIdx.x;            // 0..7   (o-group of 16)
    const int bm = blockIdx.y;            // 0..511
    const int b  = bm >> 3;
    const int m  = bm & 7;
    const int c  = blockIdx.z;            // 0..1
    const float* core = c ? core2 : core1;
    float* yout = out + (c ? Y2_OFF : Y1_OFF);
    const int woff = 4 + 8 * c;

    extern __shared__ float smem[];
    float* raw  = smem;                   // [8][32][33]  = 8448 floats (phase 1)
    float* Amat = smem + 8448;            // [16][32][33] = 16896 floats
    float* Ws   = smem + 8448 + 16896;    // [32][16]     = 512 floats

    const int tid = threadIdx.x;

    {   // 0.5*W slice
        int i  = tid >> 4;
        int oo = tid & 15;
        Ws[i * 16 + oo] =
            0.5f * weight[(size_t)i * 3072 + (woff + m) * 128 + og * 16 + oo];
    }

    // thread -> strict-upper-triangle pair (pk < pj)
    int pk = 0, pj = 0;
    if (tid < 496) {
        int rem = tid, k = 0;
        #pragma unroll 1
        while (rem >= 31 - k) { rem -= 31 - k; ++k; }
        pk = k;
        pj = k + 1 + rem;
    }

    float acc[16];
    #pragma unroll
    for (int oo = 0; oo < 16; ++oo) acc[oo] = 0.f;

    const float* cbase = core + (size_t)b * 8192 + m * 32;

    // --- phase 1: accumulate A upper triangle over i in chunks of 8 --------
    for (int ch = 0; ch < 4; ++ch) {
        __syncthreads();
        #pragma unroll
        for (int q = 0; q < 4; ++q) {
            int idx = tid + 512 * q;
            int il  = idx >> 8;
            int rem = idx & 255;
            int k   = rem >> 3;
            int j4  = rem & 7;
            const float4 v = *reinterpret_cast<const float4*>(
                cbase + (size_t)(ch * 8 + il) * 524288 + k * 256 + j4 * 4);
            float* d = &raw[(il * 32 + k) * 33 + j4 * 4];
            d[0] = v.x; d[1] = v.y; d[2] = v.z; d[3] = v.w;
        }
        __syncthreads();
        if (tid < 496) {
            #pragma unroll
            for (int il = 0; il < 8; ++il) {
                float dval = raw[(il * 32 + pj) * 33 + pk]
                           - raw[(il * 32 + pk) * 33 + pj];
                const float* wrow = &Ws[(ch * 8 + il) * 16];
                #pragma unroll
                for (int oo = 0; oo < 16; ++oo)
                    acc[oo] = fmaf(wrow[oo], dval, acc[oo]);
            }
        }
    }

    // --- mirror into smem A matrices ----------------------------------------
    if (tid < 496) {
        #pragma unroll
        for (int oo = 0; oo < 16; ++oo) {
            Amat[(oo * 32 + pk) * 33 + pj] = acc[oo];
            Amat[(oo * 32 + pj) * 33 + pk] = -acc[oo];
        }
    } else {
        int oo = tid - 496;
        #pragma unroll
        for (int dd = 0; dd < 32; ++dd)
            Amat[(oo * 32 + dd) * 33 + dd] = 0.f;
    }
    __syncthreads();

    // --- phase 2: per-warp blocked Gauss-Jordan inverse of M = I - A --------
    const int w    = tid >> 5;            // warp -> matrix index
    const int lane = tid & 31;            // lane -> row index

    float M[32];
    #pragma unroll
    for (int q = 0; q < 32; ++q)
        M[q] = (lane == q ? 1.0f : 0.0f) - Amat[(w * 32 + lane) * 33 + q];

    // Warp-private scratch aliased onto this warp's OWN (now dead) Amat rows:
    // 2 buffers x 8 rows x 36 floats = 576 <= 1056 floats per matrix slice.
    float* Sw = Amat + w * 1056;
    __syncwarp();                         // M-init loads done before STS alias

    #pragma unroll
    for (int P = 0; P < 4; ++P) {
        const int base = 8 * P;
        float* buf = Sw + (P & 1) * 288;

        // publish pre-panel rows of the 8 panel lanes (all 32 cols)
        if ((lane >> 3) == P) {
            float* row = buf + (lane & 7) * 36;
            #pragma unroll
            for (int g4 = 0; g4 < 8; ++g4)
                *reinterpret_cast<float4*>(row + g4 * 4) =
                    make_float4(M[g4 * 4 + 0], M[g4 * 4 + 1],
                                M[g4 * 4 + 2], M[g4 * 4 + 3]);
        }

        // mini-GJ restricted to panel columns [base, base+8)
        #pragma unroll
        for (int pp = 0; pp < 8; ++pp) {
            const int p = base + pp;
            float piv = __shfl_sync(0xffffffffu, M[p], p);
            float d   = __fdividef(1.0f, piv);   // pivots >= 1, always safe
            float g   = (lane == p) ? (1.0f - d) : M[p] * d;
            #pragma unroll
            for (int qq = 0; qq < 8; ++qq) {
                if (qq == pp) continue;
                const int q = base + qq;
                float prq = __shfl_sync(0xffffffffu, M[q], p);
                M[q] = fmaf(-g, prq, M[q]);
            }
            M[p] = (lane == p) ? d : -g;
        }
        __syncwarp();                     // publish visible; prev buf reads done

        // rank-8 update of the 24 non-panel columns:
        //   M[r][q] = keep * M[r][q] + sum_t E[r][base+t] * S[t][q]
        const float keep = ((lane >> 3) == P) ? 0.0f : 1.0f;
        #pragma unroll
        for (int g4 = 0; g4 < 8; ++g4) {
            if (g4 == 2 * P || g4 == 2 * P + 1) continue;   // compile-time skip
            M[g4 * 4 + 0] *= keep;
            M[g4 * 4 + 1] *= keep;
            M[g4 * 4 + 2] *= keep;
            M[g4 * 4 + 3] *= keep;
        }
        #pragma unroll
        for (int t = 0; t < 8; ++t) {
            const float h = M[base + t];              // E[lane][base+t]
            const float* srow = buf + t * 36;
            #pragma unroll
            for (int g4 = 0; g4 < 8; ++g4) {
                if (g4 == 2 * P || g4 == 2 * P + 1) continue;
                float4 s = *reinterpret_cast<const float4*>(srow + g4 * 4);
                M[g4 * 4 + 0] = fmaf(h, s.x, M[g4 * 4 + 0]);
                M[g4 * 4 + 1] = fmaf(h, s.y, M[g4 * 4 + 1]);
                M[g4 * 4 + 2] = fmaf(h, s.z, M[g4 * 4 + 2]);
                M[g4 * 4 + 3] = fmaf(h, s.w, M[g4 * 4 + 3]);
            }
        }
    }

    // --- Q = 2*Minv - I ; write row 'lane' of matrix (o, b, m) --------------
    const int o = og * 16 + w;
    float* dst = yout + ((size_t)o * 64 + b) * 8192 + lane * 256 + m * 32;
    #pragma unroll
    for (int qq = 0; qq < 8; ++qq) {
        float4 v;
        v.x = 2.f * M[qq * 4 + 0] - (lane == qq * 4 + 0 ? 1.f : 0.f);
        v.y = 2.f * M[qq * 4 + 1] - (lane == qq * 4 + 1 ? 1.f : 0.f);
        v.z = 2.f * M[qq * 4 + 2] - (lane == qq * 4 + 2 ? 1.f : 0.f);
        v.w = 2.f * M[qq * 4 + 3] - (lane == qq * 4 + 3 ? 1.f : 0.f);
        *reinterpret_cast<float4*>(dst + qq * 4) = v;
    }
}

// ---------------------------------------------------------------------------
extern "C" void kernel_launch(void* const* d_in, const int* in_sizes, int n_in,
                              void* d_out, int out_size)
{
    (void)in_sizes; (void)n_in; (void)out_size;
    const float* core0  = (const float*)d_in[0];
    const float* core1  = (const float*)d_in[1];
    const float* core2  = (const float*)d_in[2];
    const float* core3  = (const float*)d_in[3];
    const float* weight = (const float*)d_in[4];
    float* out = (float*)d_out;

    static const int SMEM_BYTES = (8448 + 16896 + 512) * 4;   // 103424 B
    cudaFuncSetAttribute(cayley_kernel,
                         cudaFuncAttributeMaxDynamicSharedMemorySize,
                         SMEM_BYTES);

    y0_kernel<<<256, 256>>>(core0, weight, out + Y0_OFF);
    y3_kernel<<<256, 256>>>(core3, weight, out + Y3_OFF);
    cayley_kernel<<<dim3(8, 512, 2), 512, SMEM_BYTES>>>(core1, core2, weight, out);
}

// round 9
// speedup vs baseline: 1.9742x; 1.0798x over previous
#include <cuda_runtime.h>
#include <cstdint>

// ---------------------------------------------------------------------------
// Problem constants
//   SHAPE = (4, 8, 8, 4), I_CH=32, O_CH=128, BATCH=64, RANK=32
//   core0: (32, 64, 1, 4, 32)   strides (floats): i 8192, b 128, m 32, j 1
//   core1: (32, 64, 32, 8, 32)  strides: i 524288, b 8192, k 256, m 32, j 1
//   core2: same as core1
//   core3: (32, 64, 32, 4, 1)   strides: i 8192, b 128, k 4, m 1
//   weight:(32, 24, 128)        strides: i 3072, row 128, o 1
// ---------------------------------------------------------------------------

static const size_t Y0_OFF = 0;
static const size_t Y1_OFF = 1048576;
static const size_t Y2_OFF = 1048576 + 67108864ull;
static const size_t Y3_OFF = 1048576 + 2ull * 67108864ull;

// ---------------------------------------------------------------------------
// y0: out0[o,b,m,j] = sum_i W[i, m, o] * core0[i,b,0,m,j]
// ---------------------------------------------------------------------------
__global__ void __launch_bounds__(256) y0_kernel(
    const float* __restrict__ core0, const float* __restrict__ weight,
    float* __restrict__ out)
{
    __shared__ float cs[32 * 32];     // [i][j]
    __shared__ float Ws[32 * 128];    // [i][o]
    const int bm = blockIdx.x;
    const int b = bm >> 2;
    const int m = bm & 3;
    const int tid = threadIdx.x;

    {
        int i = tid >> 3, j4 = tid & 7;
        float4 v = *reinterpret_cast<const float4*>(
            core0 + (size_t)i * 8192 + b * 128 + m * 32 + j4 * 4);
        *reinterpret_cast<float4*>(&cs[i * 32 + j4 * 4]) = v;
    }
    #pragma unroll
    for (int q = 0; q < 4; ++q) {
        int idx = tid + 256 * q;
        int i = idx >> 5, o4 = idx & 31;
        float4 v = *reinterpret_cast<const float4*>(
            weight + (size_t)i * 3072 + m * 128 + o4 * 4);
        *reinterpret_cast<float4*>(&Ws[i * 128 + o4 * 4]) = v;
    }
    __syncthreads();

    const int j = tid & 31;
    const int obase = (tid >> 5) * 16;
    float acc[16];
    #pragma unroll
    for (int t = 0; t < 16; ++t) acc[t] = 0.f;
    #pragma unroll 4
    for (int i = 0; i < 32; ++i) {
        float v = cs[i * 32 + j];
        #pragma unroll
        for (int oo = 0; oo < 16; ++oo)
            acc[oo] = fmaf(Ws[i * 128 + obase + oo], v, acc[oo]);
    }
    #pragma unroll
    for (int oo = 0; oo < 16; ++oo)
        out[(size_t)(obase + oo) * 8192 + b * 128 + m * 32 + j] = acc[oo];
}

// ---------------------------------------------------------------------------
// y3: out3[o,b,k,m] = sum_i W[i, 20+m, o] * core3[i,b,k,m]
// ---------------------------------------------------------------------------
__global__ void __launch_bounds__(256) y3_kernel(
    const float* __restrict__ core3, const float* __restrict__ weight,
    float* __restrict__ out)
{
    __shared__ float cs[32 * 128];    // [i][km]
    __shared__ float Ws[32 * 32 * 4]; // [i][o_local][mm]
    const int b = blockIdx.x & 63;
    const int oq = blockIdx.x >> 6;
    const int tid = threadIdx.x;

    #pragma unroll
    for (int q = 0; q < 4; ++q) {
        int idx = tid + 256 * q;
        int i = idx >> 5, km4 = idx & 31;
        float4 v = *reinterpret_cast<const float4*>(
            core3 + (size_t)i * 8192 + b * 128 + km4 * 4);
        *reinterpret_cast<float4*>(&cs[i * 128 + km4 * 4]) = v;
    }
    #pragma unroll
    for (int q = 0; q < 16; ++q) {
        int idx = tid + 256 * q;
        int i = idx >> 7;
        int rem = idx & 127;
        int mm = rem >> 5;
        int ol = rem & 31;
        Ws[(i * 32 + ol) * 4 + mm] =
            weight[(size_t)i * 3072 + (20 + mm) * 128 + oq * 32 + ol];
    }
    __syncthreads();

    const int km = tid & 127;
    const int oh = tid >> 7;
    const int mm = km & 3;
    float acc[16];
    #pragma unroll
    for (int t = 0; t < 16; ++t) acc[t] = 0.f;
    #pragma unroll 4
    for (int i = 0; i < 32; ++i) {
        float v = cs[i * 128 + km];
        #pragma unroll
        for (int oo = 0; oo < 16; ++oo)
            acc[oo] = fmaf(Ws[(i * 32 + oh * 16 + oo) * 4 + mm], v, acc[oo]);
    }
    #pragma unroll
    for (int oo = 0; oo < 16; ++oo) {
        int o = oq * 32 + oh * 16 + oo;
        out[((size_t)o * 64 + b) * 128 + km] = acc[oo];
    }
}

// ---------------------------------------------------------------------------
// cp.async helpers
// ---------------------------------------------------------------------------
__device__ __forceinline__ void cp_async16(float* smem_dst, const float* gmem_src)
{
    uint32_t s = (uint32_t)__cvta_generic_to_shared(smem_dst);
    asm volatile("cp.async.cg.shared.global [%0], [%1], 16;\n"
                 :: "r"(s), "l"(gmem_src) : "memory");
}
__device__ __forceinline__ void cp_async_commit()
{
    asm volatile("cp.async.commit_group;\n" ::: "memory");
}
template<int N>
__device__ __forceinline__ void cp_async_wait()
{
    asm volatile("cp.async.wait_group %0;\n" :: "n"(N) : "memory");
}

// ---------------------------------------------------------------------------
// Fused cores 1 & 2 (one launch per core so ncu -s5 -c1 lands on cayley):
//   A[o,k,j] = sum_i 0.5*W[i,off+m,o] * (c[i,b,j,m,k] - c[i,b,k,m,j])   (skew)
//   Q = (I-A)^{-1}(I+A) = 2*(I-A)^{-1} - I
// Phase 1: cp.async double-buffered pipeline over 8 chunks of 4 i each —
//          chunk ch+1 loads fly while chunk ch is accumulated (496 triangle
//          threads, acc[16] per thread).
// Phase 2: per-warp blocked register Gauss-Jordan (panel width 8), as R8.
// Epilogue: Q staged to smem (stride 36, 16B-aligned), re-read with a
//          lane->(4 k-rows x 8 j4) map so each STG.128 covers 4 cache lines
//          instead of 32 (L1 wavefronts per warp: 256 -> ~96).
// __launch_bounds__(512,2) keeps 2 CTAs/SM.
// No pivoting needed: sym(I-A)=I  =>  every pivot >= 1.
// ---------------------------------------------------------------------------
__global__ void __launch_bounds__(512, 2) cayley_kernel(
    const float* __restrict__ core,
    const float* __restrict__ weight,
    float* __restrict__ yout,
    int woff)
{
    const int og = blockIdx.x;            // 0..7   (o-group of 16)
    const int bm = blockIdx.y;            // 0..511
    const int b  = bm >> 3;
    const int m  = bm & 7;

    extern __shared__ float smem[];
    // Layout (floats):
    //   raw  : [2][4][32][36] = 9216   (phase-1 double buffer, stride 36)
    //   Amat : 9216 .. 26112  = 16896  ([16][32][33])
    //   Ws   : 26112 .. 26624 = 512
    //   Qstage (epilogue only, after barrier): 0 .. 18432  ([16][32][36])
    float* raw  = smem;
    float* Amat = smem + 9216;
    float* Ws   = smem + 9216 + 16896;

    const int tid = threadIdx.x;

    {   // 0.5*W slice
        int i  = tid >> 4;
        int oo = tid & 15;
        Ws[i * 16 + oo] =
            0.5f * weight[(size_t)i * 3072 + (woff + m) * 128 + og * 16 + oo];
    }

    // thread -> strict-upper-triangle pair (pk < pj)
    int pk = 0, pj = 0;
    if (tid < 496) {
        int rem = tid, k = 0;
        #pragma unroll 1
        while (rem >= 31 - k) { rem -= 31 - k; ++k; }
        pk = k;
        pj = k + 1 + rem;
    }

    float acc[16];
    #pragma unroll
    for (int oo = 0; oo < 16; ++oo) acc[oo] = 0.f;

    const float* cbase = core + (size_t)b * 8192 + m * 32;

    // per-thread cp.async source/dst indices (2 ops/thread/chunk)
    int il0, k0, j40, il1, k1, j41;
    {
        int idx = tid;
        il0 = idx >> 8; k0 = (idx & 255) >> 3; j40 = idx & 7;
        idx = tid + 512;
        il1 = idx >> 8; k1 = (idx & 255) >> 3; j41 = idx & 7;
    }

    // --- phase 1: pipelined accumulate over 8 chunks of 4 i ---------------
    // prologue: chunk 0 -> buf 0
    cp_async16(raw + (il0 * 32 + k0) * 36 + j40 * 4,
               cbase + (size_t)il0 * 524288 + k0 * 256 + j40 * 4);
    cp_async16(raw + (il1 * 32 + k1) * 36 + j41 * 4,
               cbase + (size_t)il1 * 524288 + k1 * 256 + j41 * 4);
    cp_async_commit();

    #pragma unroll 1
    for (int ch = 0; ch < 8; ++ch) {
        const int cur = ch & 1;
        if (ch < 7) {
            float* dbuf = raw + (cur ^ 1) * 4608;
            const float* src = cbase + (size_t)(ch + 1) * 4 * 524288;
            cp_async16(dbuf + (il0 * 32 + k0) * 36 + j40 * 4,
                       src + (size_t)il0 * 524288 + k0 * 256 + j40 * 4);
            cp_async16(dbuf + (il1 * 32 + k1) * 36 + j41 * 4,
                       src + (size_t)il1 * 524288 + k1 * 256 + j41 * 4);
            cp_async_commit();
            cp_async_wait<1>();           // chunk ch complete, ch+1 in flight
        } else {
            cp_async_wait<0>();
        }
        __syncthreads();                  // chunk ch visible to all threads

        if (tid < 496) {
            const float* rb = raw + cur * 4608;
            #pragma unroll
            for (int il = 0; il < 4; ++il) {
                float dval = rb[(il * 32 + pj) * 36 + pk]
                           - rb[(il * 32 + pk) * 36 + pj];
                const float* wrow = &Ws[(ch * 4 + il) * 16];
                #pragma unroll
                for (int oo = 0; oo < 16; ++oo)
                    acc[oo] = fmaf(wrow[oo], dval, acc[oo]);
            }
        }
        if (ch < 7) __syncthreads();      // reads done before buf reuse
    }

    // --- mirror into smem A matrices ----------------------------------------
    if (tid < 496) {
        #pragma unroll
        for (int oo = 0; oo < 16; ++oo) {
            Amat[(oo * 32 + pk) * 33 + pj] = acc[oo];
            Amat[(oo * 32 + pj) * 33 + pk] = -acc[oo];
        }
    } else {
        int oo = tid - 496;
        #pragma unroll
        for (int dd = 0; dd < 32; ++dd)
            Amat[(oo * 32 + dd) * 33 + dd] = 0.f;
    }
    __syncthreads();

    // --- phase 2: per-warp blocked Gauss-Jordan inverse of M = I - A --------
    const int w    = tid >> 5;            // warp -> matrix index
    const int lane = tid & 31;            // lane -> row index

    float M[32];
    #pragma unroll
    for (int q = 0; q < 32; ++q)
        M[q] = (lane == q ? 1.0f : 0.0f) - Amat[(w * 32 + lane) * 33 + q];

    // Warp-private scratch aliased onto this warp's OWN (now dead) Amat rows:
    float* Sw = Amat + w * 1056;
    __syncwarp();                         // M-init loads done before STS alias

    #pragma unroll
    for (int P = 0; P < 4; ++P) {
        const int base = 8 * P;
        float* buf = Sw + (P & 1) * 288;

        // publish pre-panel rows of the 8 panel lanes (all 32 cols)
        if ((lane >> 3) == P) {
            float* row = buf + (lane & 7) * 36;
            #pragma unroll
            for (int g4 = 0; g4 < 8; ++g4)
                *reinterpret_cast<float4*>(row + g4 * 4) =
                    make_float4(M[g4 * 4 + 0], M[g4 * 4 + 1],
                                M[g4 * 4 + 2], M[g4 * 4 + 3]);
        }

        // mini-GJ restricted to panel columns [base, base+8)
        #pragma unroll
        for (int pp = 0; pp < 8; ++pp) {
            const int p = base + pp;
            float piv = __shfl_sync(0xffffffffu, M[p], p);
            float d   = __fdividef(1.0f, piv);   // pivots >= 1, always safe
            float g   = (lane == p) ? (1.0f - d) : M[p] * d;
            #pragma unroll
            for (int qq = 0; qq < 8; ++qq) {
                if (qq == pp) continue;
                const int q = base + qq;
                float prq = __shfl_sync(0xffffffffu, M[q], p);
                M[q] = fmaf(-g, prq, M[q]);
            }
            M[p] = (lane == p) ? d : -g;
        }
        __syncwarp();                     // publish visible; prev buf reads done

        // rank-8 update of the 24 non-panel columns:
        //   M[r][q] = keep * M[r][q] + sum_t E[r][base+t] * S[t][q]
        const float keep = ((lane >> 3) == P) ? 0.0f : 1.0f;
        #pragma unroll
        for (int g4 = 0; g4 < 8; ++g4) {
            if (g4 == 2 * P || g4 == 2 * P + 1) continue;   // compile-time skip
            M[g4 * 4 + 0] *= keep;
            M[g4 * 4 + 1] *= keep;
            M[g4 * 4 + 2] *= keep;
            M[g4 * 4 + 3] *= keep;
        }
        #pragma unroll
        for (int t = 0; t < 8; ++t) {
            const float h = M[base + t];              // E[lane][base+t]
            const float* srow = buf + t * 36;
            #pragma unroll
            for (int g4 = 0; g4 < 8; ++g4) {
                if (g4 == 2 * P || g4 == 2 * P + 1) continue;
                float4 s = *reinterpret_cast<const float4*>(srow + g4 * 4);
                M[g4 * 4 + 0] = fmaf(h, s.x, M[g4 * 4 + 0]);
                M[g4 * 4 + 1] = fmaf(h, s.y, M[g4 * 4 + 1]);
                M[g4 * 4 + 2] = fmaf(h, s.z, M[g4 * 4 + 2]);
                M[g4 * 4 + 3] = fmaf(h, s.w, M[g4 * 4 + 3]);
            }
        }
    }

    // --- epilogue: Q = 2*Minv - I staged to smem, then coalesced stores ----
    __syncthreads();                      // all Sw scratch dead block-wide
    {
        float* qrow = smem + w * 1152 + lane * 36;
        #pragma unroll
        for (int q4 = 0; q4 < 8; ++q4) {
            float4 v;
            v.x = 2.f * M[q4 * 4 + 0] - (lane == q4 * 4 + 0 ? 1.f : 0.f);
            v.y = 2.f * M[q4 * 4 + 1] - (lane == q4 * 4 + 1 ? 1.f : 0.f);
            v.z = 2.f * M[q4 * 4 + 2] - (lane == q4 * 4 + 2 ? 1.f : 0.f);
            v.w = 2.f * M[q4 * 4 + 3] - (lane == q4 * 4 + 3 ? 1.f : 0.f);
            *reinterpret_cast<float4*>(qrow + q4 * 4) = v;
        }
    }
    __syncwarp();                         // warp-private region: syncwarp ok
    {
        const int o = og * 16 + w;
        float* obase = yout + ((size_t)o * 64 + b) * 8192 + m * 32;
        const int krow_lo = lane >> 3;    // 0..3
        const int j4      = lane & 7;     // 0..7
        const float* qbase = smem + w * 1152;
        #pragma unroll
        for (int it = 0; it < 8; ++it) {
            const int krow = it * 4 + krow_lo;
            float4 v = *reinterpret_cast<const float4*>(
                qbase + krow * 36 + j4 * 4);
            *reinterpret_cast<float4*>(obase + krow * 256 + j4 * 4) = v;
        }
    }
}

// ---------------------------------------------------------------------------
extern "C" void kernel_launch(void* const* d_in, const int* in_sizes, int n_in,
                              void* d_out, int out_size)
{
    (void)in_sizes; (void)n_in; (void)out_size;
    const float* core0  = (const float*)d_in[0];
    const float* core1  = (const float*)d_in[1];
    const float* core2  = (const float*)d_in[2];
    const float* core3  = (const float*)d_in[3];
    const float* weight = (const float*)d_in[4];
    float* out = (float*)d_out;

    static const int SMEM_BYTES = (9216 + 16896 + 512) * 4;   // 106496 B
    cudaFuncSetAttribute(cayley_kernel,
                         cudaFuncAttributeMaxDynamicSharedMemorySize,
                         SMEM_BYTES);

    // cayley launches first (and split per core) so ncu -s5 -c1 captures one
    cayley_kernel<<<dim3(8, 512, 1), 512, SMEM_BYTES>>>(
        core1, weight, out + Y1_OFF, 4);
    cayley_kernel<<<dim3(8, 512, 1), 512, SMEM_BYTES>>>(
        core2, weight, out + Y2_OFF, 12);
    y0_kernel<<<256, 256>>>(core0, weight, out + Y0_OFF);
    y3_kernel<<<256, 256>>>(core3, weight, out + Y3_OFF);
}